// round 12
// baseline (speedup 1.0000x reference)
#include <cuda_runtime.h>
#include <cuda_bf16.h>
#include <utility>
#include <cstddef>

// ---------------------------------------------------------------------------
// Compile-time reproduction of the reference codebook.
// reference: np.random.RandomState(0).choice([1.0f,3.0f], size=(512,8))
// Legacy randint path: masked 32-bit MT19937 draws, bit = tempered() & 1.
// Only the 8-bit PATTERN matters; duplicates dequantize identically.
// (Confirmed: R1-R11 rel_err ~6e-8.)
//
// R6 LESSON: cross-group comparison MUST use the exact score form
// u * |u| * (1/(8+8k)); inexact normalization flips near-ties (5e-4).
// R8 LESSON: device code reads host constexpr tables only via constexpr
// locals / template args.
// R10: max-then-add factored cells are VALUE-exact (rounding monotonicity).
// R11: round-robin interleave across groups (bit-identical permutation).
// R12: (a) first-cell direct assignment kills gmax/qid init + 9 tracks;
//      (b) resolve via smem DP table (2 LDS + FADD per candidate) — values
//      bit-identical to scan values; moves ~70 ops to the idle LSU pipe.
// ---------------------------------------------------------------------------

struct Tables { bool present[256]; };

__host__ __device__ constexpr unsigned mt_temper(unsigned y) {
    y ^= (y >> 11);
    y ^= (y << 7)  & 0x9d2c5680u;
    y ^= (y << 15) & 0xefc60000u;
    y ^= (y >> 18);
    return y;
}

__host__ __device__ constexpr Tables make_tables() {
    unsigned mt[624] = {};
    {
        unsigned s = 0u;  // seed = 0
        for (int i = 0; i < 624; ++i) {
            mt[i] = s;
            s = 1812433253u * (s ^ (s >> 30)) + (unsigned)(i + 1);
        }
    }
    int pos = 624;
    Tables t{};
    for (int i = 0; i < 256; ++i) t.present[i] = false;
    for (int r = 0; r < 512; ++r) {
        unsigned p = 0;
        for (int j = 0; j < 8; ++j) {
            if (pos == 624) {
                for (int i = 0; i < 624; ++i) {
                    unsigned y = (mt[i] & 0x80000000u) | (mt[(i + 1) % 624] & 0x7fffffffu);
                    mt[i] = mt[(i + 397) % 624] ^ (y >> 1) ^ ((y & 1u) ? 0x9908b0dfu : 0u);
                }
                pos = 0;
            }
            unsigned bit = mt_temper(mt[pos++]) & 1u;
            p |= bit << j;
        }
        t.present[p] = true;
    }
    return t;
}

constexpr Tables TBL = make_tables();

__host__ __device__ constexpr int popc8(int p) {
    int k = 0;
    for (int j = 0; j < 8; ++j) k += (p >> j) & 1;
    return k;
}

// ---------------------------------------------------------------------------
// Compile-time cell table (R10 construction).
// ---------------------------------------------------------------------------
struct CellTab {
    int n;
    int k[224];
    int isL[224];
    int shared[224];
    int mem[224][4];
    int cnt[224];
    int pat[224][4];
};

__host__ __device__ constexpr CellTab make_cells() {
    CellTab t{};
    t.n = 0;
    for (int K = 0; K <= 8; ++K) {
        int singles[64] = {};
        int ns = 0;
        for (int H = 0; H < 16; ++H) {
            int ls[16] = {};
            int m = 0;
            for (int L = 0; L < 16; ++L) {
                int P = (H << 4) | L;
                if (TBL.present[P] && popc8(P) == K) ls[m++] = L;
            }
            int i = 0;
            while (i < m) {
                int c = (m - i >= 4) ? 4 : (m - i);
                if (c == 1) { singles[ns++] = (H << 4) | ls[i]; i += 1; continue; }
                int id = t.n++;
                t.k[id] = K; t.isL[id] = 0; t.shared[id] = H; t.cnt[id] = c;
                for (int j = 0; j < 4; ++j) {
                    int L = ls[i + (j < c ? j : c - 1)];
                    t.mem[id][j] = L;
                    t.pat[id][j] = (H << 4) | L;
                }
                i += c;
            }
        }
        for (int L = 0; L < 16; ++L) {
            int hs[16] = {};
            int m = 0;
            for (int si = 0; si < ns; ++si)
                if ((singles[si] & 15) == L) hs[m++] = singles[si] >> 4;
            int i = 0;
            while (i < m) {
                int c = (m - i >= 4) ? 4 : (m - i);
                int id = t.n++;
                t.k[id] = K; t.isL[id] = 1; t.shared[id] = L; t.cnt[id] = c;
                for (int j = 0; j < 4; ++j) {
                    int H = hs[i + (j < c ? j : c - 1)];
                    t.mem[id][j] = H;
                    t.pat[id][j] = (H << 4) | L;
                }
                i += c;
            }
        }
    }
    return t;
}

constexpr CellTab CT = make_cells();

// ---------------------------------------------------------------------------
// R11 round-robin emission order (bit-identical permutation).
// ---------------------------------------------------------------------------
struct Order { int idx[224]; };

__host__ __device__ constexpr Order make_order() {
    Order o{};
    int ids[9][64] = {};
    int cg[9] = {};
    for (int i = 0; i < CT.n; ++i) {
        int g = CT.k[i];
        ids[g][cg[g]++] = i;
    }
    int ptr[9] = {};
    int e = 0;
    while (e < CT.n) {
        for (int g = 0; g < 9; ++g) {
            if (ptr[g] < cg[g]) o.idx[e++] = ids[g][ptr[g]++];
        }
    }
    return o;
}

constexpr Order ORD = make_order();

// First emission of this cell's popcount group in ORD order?
__host__ __device__ constexpr bool first_occ(int pos) {
    int g = CT.k[ORD.idx[pos]];
    for (int e = 0; e < pos; ++e)
        if (CT.k[ORD.idx[e]] == g) return false;
    return true;
}

__host__ __device__ constexpr bool group_empty(int K) {
    for (int i = 0; i < CT.n; ++i)
        if (CT.k[i] == K) return false;
    return true;
}

// ---------------------------------------------------------------------------
// Per-thread scan state (compile-time indexed -> registers).
// ---------------------------------------------------------------------------
struct St {
    float ulo[16];
    float th2[16];
    float gmax[9];
    unsigned qid[9];
};

template <int I, bool FIRST>
__device__ __forceinline__ void cstep(St& s) {
    constexpr int K   = CT.k[I];
    constexpr int c   = CT.cnt[I];
    constexpr int IsL = CT.isL[I];
    constexpr int SH  = CT.shared[I];
    constexpr int M0  = CT.mem[I][0];
    constexpr int M1  = CT.mem[I][1];
    constexpr int M2  = CT.mem[I][2];
    constexpr int M3  = CT.mem[I][3];
    constexpr unsigned qid =
        (unsigned)CT.pat[I][0] | ((unsigned)CT.pat[I][1] << 8) |
        ((unsigned)CT.pat[I][2] << 16) | ((unsigned)CT.pat[I][3] << 24);
    float m;
    if constexpr (IsL == 0) {
        m = s.ulo[M0];
        if constexpr (c > 1) m = fmaxf(m, s.ulo[M1]);
        if constexpr (c > 2) m = fmaxf(m, s.ulo[M2]);
        if constexpr (c > 3) m = fmaxf(m, s.ulo[M3]);
        if constexpr (SH != 0) m = m + s.th2[SH];
    } else {
        m = s.th2[M0];
        if constexpr (c > 1) m = fmaxf(m, s.th2[M1]);
        if constexpr (c > 2) m = fmaxf(m, s.th2[M2]);
        if constexpr (c > 3) m = fmaxf(m, s.th2[M3]);
        m = m + s.ulo[SH];
    }
    if constexpr (FIRST) {
        // First cell of its group: direct assignment (identical to
        // comparing against -1 init, which m >= 0 always beats).
        s.gmax[K] = m;
        s.qid[K]  = qid;
    } else {
        float old = s.gmax[K];
        s.gmax[K] = fmaxf(old, m);
        s.qid[K] = (m > old) ? qid : s.qid[K];
    }
}

template <int I>
__device__ __forceinline__ void ostep(St& s) {
    if constexpr (I < CT.n) {
        constexpr int J = ORD.idx[I];
        constexpr bool F = first_occ(I);
        cstep<J, F>(s);
    }
}

template <size_t... Is>
__device__ __forceinline__ void run_all(St& s, std::index_sequence<Is...>) {
    (ostep<(int)Is>(s), ...);
}

// Emit -1 init only for groups with no cells (phase-2 then scores them < 0).
template <int K>
__device__ __forceinline__ void init_empty(St& s) {
    if constexpr (K < 9 && group_empty(K)) { s.gmax[K] = -1.f; s.qid[K] = 0u; }
}

// ---------------------------------------------------------------------------
// Main kernel: one thread per 8-element block, 128-thread CTAs.
// Per-thread 33-float smem row (stride 33 => conflict-free banks).
// ---------------------------------------------------------------------------
__global__ void __launch_bounds__(128)
iq2xs_kernel(const float* __restrict__ w, float* __restrict__ out, int nb) {
    __shared__ float tab[128 * 33];
    int b = blockIdx.x * 128 + threadIdx.x;
    if (b >= nb) return;

    const float4* w4 = reinterpret_cast<const float4*>(w) + 2 * (size_t)b;
    float4 v0 = w4[0];
    float4 v1 = w4[1];

    // Doubled magnitudes: a2[i] = |w_i| + |w_i| (FADD with abs modifiers).
    float a2[8] = {fabsf(v0.x) + fabsf(v0.x), fabsf(v0.y) + fabsf(v0.y),
                   fabsf(v0.z) + fabsf(v0.z), fabsf(v0.w) + fabsf(v0.w),
                   fabsf(v1.x) + fabsf(v1.x), fabsf(v1.y) + fabsf(v1.y),
                   fabsf(v1.z) + fabsf(v1.z), fabsf(v1.w) + fabsf(v1.w)};

    // Subset-sum DP on doubled magnitudes (exactly 2x the undoubled sums).
    float tlo2[16], thi2[16];
    tlo2[0] = 0.f;
    tlo2[1] = a2[0];
    tlo2[2] = a2[1];
    tlo2[3] = tlo2[1] + a2[1];
    tlo2[4] = a2[2];
    tlo2[5] = tlo2[1] + a2[2];
    tlo2[6] = tlo2[2] + a2[2];
    tlo2[7] = tlo2[3] + a2[2];
#pragma unroll
    for (int m = 0; m < 8; ++m) tlo2[8 + m] = tlo2[m] + a2[3];

    thi2[0] = 0.f;
    thi2[1] = a2[4];
    thi2[2] = a2[5];
    thi2[3] = thi2[1] + a2[5];
    thi2[4] = a2[6];
    thi2[5] = thi2[1] + a2[6];
    thi2[6] = thi2[2] + a2[6];
    thi2[7] = thi2[3] + a2[6];
#pragma unroll
    for (int m = 0; m < 8; ++m) thi2[8 + m] = thi2[m] + a2[7];

    // S = sum of |w| (exact halving of the doubled total)
    float S = 0.5f * (tlo2[15] + thi2[15]);

    St s;
#pragma unroll
    for (int l = 0; l < 16; ++l) s.ulo[l] = S + tlo2[l];   // == fmaf(2,tlo,S)
#pragma unroll
    for (int h = 0; h < 16; ++h) s.th2[h] = thi2[h];       // == 2*thi

    // Spill DP tables to smem for the resolve (LSU pipe; hidden by scan).
    int tb = threadIdx.x * 33;
#pragma unroll
    for (int l = 0; l < 16; ++l) tab[tb + l] = s.ulo[l];
#pragma unroll
    for (int h = 0; h < 16; ++h) tab[tb + 16 + h] = s.th2[h];

    // Init only for empty groups (if any); others direct-assigned in scan.
    init_empty<0>(s); init_empty<1>(s); init_empty<2>(s);
    init_empty<3>(s); init_empty<4>(s); init_empty<5>(s);
    init_empty<6>(s); init_empty<7>(s); init_empty<8>(s);

    // Phase 1: fully unrolled factored-cell scan, round-robin interleaved.
    run_all(s, std::make_index_sequence<224>{});

    // Phase 2 (EXACT R4 form): score = u * |u| * (1/(8+8k)); empty groups
    // carry gmax = -1 -> sc < 0 and never beat a real group (u >= 0).
    float bestSc = -1e30f;
    unsigned bestQ = 0u;
#pragma unroll
    for (int k = 0; k < 9; ++k) {
        float g = s.gmax[k];
        float sc = g * fabsf(g) * (1.f / (8.f + 8.f * (float)k));
        float oldSc = bestSc;
        bestSc = fmaxf(oldSc, sc);
        bestQ = (sc > oldSc) ? s.qid[k] : bestQ;
    }

    // Phase 3: resolve within the winning cell via the smem DP table.
    // u(P) = ulo[P&15] + th2[P>>4] -- BIT-IDENTICAL to the scan's values
    // (FADD commutes; H==0 adds th2[0]=0 exactly). Ascending byte order +
    // strict '>' keeps first-wins; padded duplicates tie and skip.
    int bestP;
    float bestU;
    {
        int P = (int)(bestQ & 255u);
        bestU = tab[tb + (P & 15)] + tab[tb + 16 + (P >> 4)];
        bestP = P;
    }
#pragma unroll
    for (int j = 1; j < 4; ++j) {
        int P = (int)((bestQ >> (8 * j)) & 255u);
        float u = tab[tb + (P & 15)] + tab[tb + 16 + (P >> 4)];
        if (u > bestU) { bestU = u; bestP = P; }
    }

    // Least-squares scale; norm recomputed exactly from the winning popcount.
    float norm = (float)(8 * (1 + __popc((unsigned)bestP)));
    float scale = bestU / norm;
    float s3 = 3.f * scale;

    // Reload w (L1 hit) and emit STE output: w + (deq - w), reference
    // rounding order. sign(+-0)=0 -> deq 0.
    v0 = w4[0];
    v1 = w4[1];
    float wv[8] = {v0.x, v0.y, v0.z, v0.w, v1.x, v1.y, v1.z, v1.w};

    float o[8];
#pragma unroll
    for (int i = 0; i < 8; ++i) {
        float m = ((bestP >> i) & 1) ? s3 : scale;
        float deq = (wv[i] == 0.f) ? 0.f : copysignf(m, wv[i]);
        o[i] = wv[i] + (deq - wv[i]);
    }

    float4 r0 = {o[0], o[1], o[2], o[3]};
    float4 r1 = {o[4], o[5], o[6], o[7]};
    float4* out4 = reinterpret_cast<float4*>(out) + 2 * (size_t)b;
    out4[0] = r0;
    out4[1] = r1;
}

extern "C" void kernel_launch(void* const* d_in, const int* in_sizes, int n_in,
                              void* d_out, int out_size) {
    const float* w = (const float*)d_in[0];
    float* out = (float*)d_out;
    int n = in_sizes[0];
    int nb = n / 8;
    int threads = 128;
    int blocks = (nb + threads - 1) / threads;
    iq2xs_kernel<<<blocks, threads>>>(w, out, nb);
}

// round 14
// speedup vs baseline: 1.0934x; 1.0934x over previous
#include <cuda_runtime.h>
#include <cuda_bf16.h>
#include <utility>
#include <cstddef>

// ---------------------------------------------------------------------------
// Compile-time reproduction of the reference codebook.
// reference: np.random.RandomState(0).choice([1.0f,3.0f], size=(512,8))
// Legacy randint path: masked 32-bit MT19937 draws, bit = tempered() & 1.
// Only the 8-bit PATTERN matters; duplicates dequantize identically.
// (Confirmed: R1-R12 rel_err ~6e-8.)
//
// R6 LESSON: cross-group comparison MUST use the exact score form
// u * |u| * (1/(8+8k)); inexact normalization flips near-ties (5e-4).
// R8 LESSON: device code reads host constexpr tables only via constexpr
// locals / template args.
// R10: max-then-add factored cells are VALUE-exact (rounding monotonicity).
// R11: round-robin interleave across groups (bit-identical permutation).
// R12 LESSON: smem resolve trades alu ops for LSU issue slots -- net loss;
// keep the wv-recompute resolve. Direct first-assignment is the keeper.
// ---------------------------------------------------------------------------

struct Tables { bool present[256]; };

__host__ __device__ constexpr unsigned mt_temper(unsigned y) {
    y ^= (y >> 11);
    y ^= (y << 7)  & 0x9d2c5680u;
    y ^= (y << 15) & 0xefc60000u;
    y ^= (y >> 18);
    return y;
}

__host__ __device__ constexpr Tables make_tables() {
    unsigned mt[624] = {};
    {
        unsigned s = 0u;  // seed = 0
        for (int i = 0; i < 624; ++i) {
            mt[i] = s;
            s = 1812433253u * (s ^ (s >> 30)) + (unsigned)(i + 1);
        }
    }
    int pos = 624;
    Tables t{};
    for (int i = 0; i < 256; ++i) t.present[i] = false;
    for (int r = 0; r < 512; ++r) {
        unsigned p = 0;
        for (int j = 0; j < 8; ++j) {
            if (pos == 624) {
                for (int i = 0; i < 624; ++i) {
                    unsigned y = (mt[i] & 0x80000000u) | (mt[(i + 1) % 624] & 0x7fffffffu);
                    mt[i] = mt[(i + 397) % 624] ^ (y >> 1) ^ ((y & 1u) ? 0x9908b0dfu : 0u);
                }
                pos = 0;
            }
            unsigned bit = mt_temper(mt[pos++]) & 1u;
            p |= bit << j;
        }
        t.present[p] = true;
    }
    return t;
}

constexpr Tables TBL = make_tables();

__host__ __device__ constexpr int popc8(int p) {
    int k = 0;
    for (int j = 0; j < 8; ++j) k += (p >> j) & 1;
    return k;
}

// ---------------------------------------------------------------------------
// Compile-time cell table (R10 construction). A cell = up to 4 same-popcount
// patterns sharing H (H-cell: max over ulo[L] then + th2[H]) or sharing L
// (L-cell: max over th2[H] then + ulo[L], built from pass-1 singletons).
// ---------------------------------------------------------------------------
struct CellTab {
    int n;
    int k[224];
    int isL[224];
    int shared[224];
    int mem[224][4];
    int cnt[224];
    int pat[224][4];
};

__host__ __device__ constexpr CellTab make_cells() {
    CellTab t{};
    t.n = 0;
    for (int K = 0; K <= 8; ++K) {
        int singles[64] = {};
        int ns = 0;
        for (int H = 0; H < 16; ++H) {
            int ls[16] = {};
            int m = 0;
            for (int L = 0; L < 16; ++L) {
                int P = (H << 4) | L;
                if (TBL.present[P] && popc8(P) == K) ls[m++] = L;
            }
            int i = 0;
            while (i < m) {
                int c = (m - i >= 4) ? 4 : (m - i);
                if (c == 1) { singles[ns++] = (H << 4) | ls[i]; i += 1; continue; }
                int id = t.n++;
                t.k[id] = K; t.isL[id] = 0; t.shared[id] = H; t.cnt[id] = c;
                for (int j = 0; j < 4; ++j) {
                    int L = ls[i + (j < c ? j : c - 1)];
                    t.mem[id][j] = L;
                    t.pat[id][j] = (H << 4) | L;
                }
                i += c;
            }
        }
        for (int L = 0; L < 16; ++L) {
            int hs[16] = {};
            int m = 0;
            for (int si = 0; si < ns; ++si)
                if ((singles[si] & 15) == L) hs[m++] = singles[si] >> 4;
            int i = 0;
            while (i < m) {
                int c = (m - i >= 4) ? 4 : (m - i);
                int id = t.n++;
                t.k[id] = K; t.isL[id] = 1; t.shared[id] = L; t.cnt[id] = c;
                for (int j = 0; j < 4; ++j) {
                    int H = hs[i + (j < c ? j : c - 1)];
                    t.mem[id][j] = H;
                    t.pat[id][j] = (H << 4) | L;
                }
                i += c;
            }
        }
    }
    return t;
}

constexpr CellTab CT = make_cells();

// ---------------------------------------------------------------------------
// R11 round-robin emission order (bit-identical permutation).
// ---------------------------------------------------------------------------
struct Order { int idx[224]; };

__host__ __device__ constexpr Order make_order() {
    Order o{};
    int ids[9][64] = {};
    int cg[9] = {};
    for (int i = 0; i < CT.n; ++i) {
        int g = CT.k[i];
        ids[g][cg[g]++] = i;
    }
    int ptr[9] = {};
    int e = 0;
    while (e < CT.n) {
        for (int g = 0; g < 9; ++g) {
            if (ptr[g] < cg[g]) o.idx[e++] = ids[g][ptr[g]++];
        }
    }
    return o;
}

constexpr Order ORD = make_order();

// First emission of this cell's popcount group in ORD order?
__host__ __device__ constexpr bool first_occ(int pos) {
    int g = CT.k[ORD.idx[pos]];
    for (int e = 0; e < pos; ++e)
        if (CT.k[ORD.idx[e]] == g) return false;
    return true;
}

__host__ __device__ constexpr bool group_empty(int K) {
    for (int i = 0; i < CT.n; ++i)
        if (CT.k[i] == K) return false;
    return true;
}

// ---------------------------------------------------------------------------
// Per-thread scan state (compile-time indexed -> registers).
// ---------------------------------------------------------------------------
struct St {
    float ulo[16];
    float th2[16];
    float gmax[9];
    unsigned qid[9];
};

template <int I, bool FIRST>
__device__ __forceinline__ void cstep(St& s) {
    constexpr int K   = CT.k[I];
    constexpr int c   = CT.cnt[I];
    constexpr int IsL = CT.isL[I];
    constexpr int SH  = CT.shared[I];
    constexpr int M0  = CT.mem[I][0];
    constexpr int M1  = CT.mem[I][1];
    constexpr int M2  = CT.mem[I][2];
    constexpr int M3  = CT.mem[I][3];
    constexpr unsigned qid =
        (unsigned)CT.pat[I][0] | ((unsigned)CT.pat[I][1] << 8) |
        ((unsigned)CT.pat[I][2] << 16) | ((unsigned)CT.pat[I][3] << 24);
    float m;
    if constexpr (IsL == 0) {
        m = s.ulo[M0];
        if constexpr (c > 1) m = fmaxf(m, s.ulo[M1]);
        if constexpr (c > 2) m = fmaxf(m, s.ulo[M2]);
        if constexpr (c > 3) m = fmaxf(m, s.ulo[M3]);
        if constexpr (SH != 0) m = m + s.th2[SH];
    } else {
        m = s.th2[M0];
        if constexpr (c > 1) m = fmaxf(m, s.th2[M1]);
        if constexpr (c > 2) m = fmaxf(m, s.th2[M2]);
        if constexpr (c > 3) m = fmaxf(m, s.th2[M3]);
        m = m + s.ulo[SH];
    }
    if constexpr (FIRST) {
        // First cell of its group: direct assignment (identical to the old
        // compare-vs-(-1) init since m >= 0 > -1 always wins).
        s.gmax[K] = m;
        s.qid[K]  = qid;
    } else {
        float old = s.gmax[K];
        s.gmax[K] = fmaxf(old, m);
        s.qid[K] = (m > old) ? qid : s.qid[K];
    }
}

template <int I>
__device__ __forceinline__ void ostep(St& s) {
    if constexpr (I < CT.n) {
        constexpr int J = ORD.idx[I];
        constexpr bool F = first_occ(I);
        cstep<J, F>(s);
    }
}

template <size_t... Is>
__device__ __forceinline__ void run_all(St& s, std::index_sequence<Is...>) {
    (ostep<(int)Is>(s), ...);
}

// Emit -1 init only for groups with no cells (phase-2 then scores them < 0).
template <int K>
__device__ __forceinline__ void init_empty(St& s) {
    if constexpr (K < 9 && group_empty(K)) { s.gmax[K] = -1.f; s.qid[K] = 0u; }
}

// ---------------------------------------------------------------------------
// Main kernel: one thread per 8-element block. 128-thread CTAs; NO
// min-blocks clause (R5 lesson: reg caps cause spills), NO smem (R12).
// ---------------------------------------------------------------------------
__global__ void __launch_bounds__(128)
iq2xs_kernel(const float* __restrict__ w, float* __restrict__ out, int nb) {
    int b = blockIdx.x * 128 + threadIdx.x;
    if (b >= nb) return;

    const float4* w4 = reinterpret_cast<const float4*>(w) + 2 * (size_t)b;
    float4 v0 = w4[0];
    float4 v1 = w4[1];

    // Doubled magnitudes: a2[i] = |w_i| + |w_i| (FADD with abs modifiers).
    float a2[8] = {fabsf(v0.x) + fabsf(v0.x), fabsf(v0.y) + fabsf(v0.y),
                   fabsf(v0.z) + fabsf(v0.z), fabsf(v0.w) + fabsf(v0.w),
                   fabsf(v1.x) + fabsf(v1.x), fabsf(v1.y) + fabsf(v1.y),
                   fabsf(v1.z) + fabsf(v1.z), fabsf(v1.w) + fabsf(v1.w)};

    // Subset-sum DP on doubled magnitudes (exactly 2x the undoubled sums).
    float tlo2[16], thi2[16];
    tlo2[0] = 0.f;
    tlo2[1] = a2[0];
    tlo2[2] = a2[1];
    tlo2[3] = tlo2[1] + a2[1];
    tlo2[4] = a2[2];
    tlo2[5] = tlo2[1] + a2[2];
    tlo2[6] = tlo2[2] + a2[2];
    tlo2[7] = tlo2[3] + a2[2];
#pragma unroll
    for (int m = 0; m < 8; ++m) tlo2[8 + m] = tlo2[m] + a2[3];

    thi2[0] = 0.f;
    thi2[1] = a2[4];
    thi2[2] = a2[5];
    thi2[3] = thi2[1] + a2[5];
    thi2[4] = a2[6];
    thi2[5] = thi2[1] + a2[6];
    thi2[6] = thi2[2] + a2[6];
    thi2[7] = thi2[3] + a2[6];
#pragma unroll
    for (int m = 0; m < 8; ++m) thi2[8 + m] = thi2[m] + a2[7];

    // S = sum of |w| (exact halving of the doubled total)
    float S = 0.5f * (tlo2[15] + thi2[15]);

    St s;
#pragma unroll
    for (int l = 0; l < 16; ++l) s.ulo[l] = S + tlo2[l];   // == fmaf(2,tlo,S)
#pragma unroll
    for (int h = 0; h < 16; ++h) s.th2[h] = thi2[h];       // == 2*thi

    // Init only for empty groups (if any); others direct-assigned in scan.
    init_empty<0>(s); init_empty<1>(s); init_empty<2>(s);
    init_empty<3>(s); init_empty<4>(s); init_empty<5>(s);
    init_empty<6>(s); init_empty<7>(s); init_empty<8>(s);

    // Phase 1: fully unrolled factored-cell scan, round-robin interleaved.
    run_all(s, std::make_index_sequence<224>{});

    // Phase 2 (EXACT R4 form): score = u * |u| * (1/(8+8k)); empty groups
    // carry gmax = -1 -> sc < 0 and never beat a real group (u >= 0).
    float bestSc = -1e30f;
    unsigned bestQ = 0u;
#pragma unroll
    for (int k = 0; k < 9; ++k) {
        float g = s.gmax[k];
        float sc = g * fabsf(g) * (1.f / (8.f + 8.f * (float)k));
        float oldSc = bestSc;
        bestSc = fmaxf(oldSc, sc);
        bestQ = (sc > oldSc) ? s.qid[k] : bestQ;
    }

    // Reload w (L1 hit) for resolve + epilogue.
    v0 = w4[0];
    v1 = w4[1];
    float wv[8] = {v0.x, v0.y, v0.z, v0.w, v1.x, v1.y, v1.z, v1.w};

    // Phase 3: resolve within the winning cell (branchless, 4 candidates,
    // wv-recompute -- the R11 form). Ascending byte order + strict '>' keeps
    // first-wins; padded duplicates tie and skip.
    int bestP = (int)(bestQ & 255u);
    float bestU;
    {
        float t = 0.f;
#pragma unroll
        for (int i = 0; i < 8; ++i)
            if (bestP & (1 << i)) t += fabsf(wv[i]);
        bestU = fmaf(2.f, t, S);
    }
#pragma unroll
    for (int j = 1; j < 4; ++j) {
        int P = (int)((bestQ >> (8 * j)) & 255u);
        float t = 0.f;
#pragma unroll
        for (int i = 0; i < 8; ++i)
            if (P & (1 << i)) t += fabsf(wv[i]);
        float u = fmaf(2.f, t, S);
        if (u > bestU) { bestU = u; bestP = P; }
    }

    // Least-squares scale; norm recomputed exactly from the winning popcount.
    float norm = (float)(8 * (1 + __popc((unsigned)bestP)));
    float scale = bestU / norm;
    float s3 = 3.f * scale;

    // STE output: w + (deq - w), reference rounding order. sign(+-0)=0 -> deq 0.
    float o[8];
#pragma unroll
    for (int i = 0; i < 8; ++i) {
        float m = ((bestP >> i) & 1) ? s3 : scale;
        float deq = (wv[i] == 0.f) ? 0.f : copysignf(m, wv[i]);
        o[i] = wv[i] + (deq - wv[i]);
    }

    float4 r0 = {o[0], o[1], o[2], o[3]};
    float4 r1 = {o[4], o[5], o[6], o[7]};
    float4* out4 = reinterpret_cast<float4*>(out) + 2 * (size_t)b;
    out4[0] = r0;
    out4[1] = r1;
}

extern "C" void kernel_launch(void* const* d_in, const int* in_sizes, int n_in,
                              void* d_out, int out_size) {
    const float* w = (const float*)d_in[0];
    float* out = (float*)d_out;
    int n = in_sizes[0];
    int nb = n / 8;
    int threads = 128;
    int blocks = (nb + threads - 1) / threads;
    iq2xs_kernel<<<blocks, threads>>>(w, out, nb);
}

// round 17
// speedup vs baseline: 1.0957x; 1.0021x over previous
#include <cuda_runtime.h>
#include <cuda_bf16.h>
#include <utility>
#include <cstddef>

// ---------------------------------------------------------------------------
// Compile-time reproduction of the reference codebook.
// reference: np.random.RandomState(0).choice([1.0f,3.0f], size=(512,8))
// Legacy randint path: masked 32-bit MT19937 draws, bit = tempered() & 1.
// Only the 8-bit PATTERN matters; duplicates dequantize identically.
// (Confirmed: R1-R14 rel_err ~6e-8.)
//
// R6 LESSON: cross-group comparison MUST use the exact score form
// u * |u| * (1/(8+8k)); inexact normalization flips near-ties (5e-4).
// R8 LESSON: device code reads host constexpr tables only via constexpr
// locals / template args.
// R10: max-then-add factored cells are VALUE-exact (rounding monotonicity).
// R11: round-robin interleave across groups (bit-identical permutation).
// R12 LESSON: smem resolve trades alu ops for LSU issue slots -- net loss.
// R14: first-cell direct assignment (keeper).
// R15: output deq directly (STE round-trip is ulp-level, output-only);
//      phase-2 first-group direct assign.
// ---------------------------------------------------------------------------

struct Tables { bool present[256]; };

__host__ __device__ constexpr unsigned mt_temper(unsigned y) {
    y ^= (y >> 11);
    y ^= (y << 7)  & 0x9d2c5680u;
    y ^= (y << 15) & 0xefc60000u;
    y ^= (y >> 18);
    return y;
}

__host__ __device__ constexpr Tables make_tables() {
    unsigned mt[624] = {};
    {
        unsigned s = 0u;  // seed = 0
        for (int i = 0; i < 624; ++i) {
            mt[i] = s;
            s = 1812433253u * (s ^ (s >> 30)) + (unsigned)(i + 1);
        }
    }
    int pos = 624;
    Tables t{};
    for (int i = 0; i < 256; ++i) t.present[i] = false;
    for (int r = 0; r < 512; ++r) {
        unsigned p = 0;
        for (int j = 0; j < 8; ++j) {
            if (pos == 624) {
                for (int i = 0; i < 624; ++i) {
                    unsigned y = (mt[i] & 0x80000000u) | (mt[(i + 1) % 624] & 0x7fffffffu);
                    mt[i] = mt[(i + 397) % 624] ^ (y >> 1) ^ ((y & 1u) ? 0x9908b0dfu : 0u);
                }
                pos = 0;
            }
            unsigned bit = mt_temper(mt[pos++]) & 1u;
            p |= bit << j;
        }
        t.present[p] = true;
    }
    return t;
}

constexpr Tables TBL = make_tables();

__host__ __device__ constexpr int popc8(int p) {
    int k = 0;
    for (int j = 0; j < 8; ++j) k += (p >> j) & 1;
    return k;
}

// ---------------------------------------------------------------------------
// Compile-time cell table (R10 construction). A cell = up to 4 same-popcount
// patterns sharing H (H-cell: max over ulo[L] then + th2[H]) or sharing L
// (L-cell: max over th2[H] then + ulo[L], built from pass-1 singletons).
// ---------------------------------------------------------------------------
struct CellTab {
    int n;
    int k[224];
    int isL[224];
    int shared[224];
    int mem[224][4];
    int cnt[224];
    int pat[224][4];
};

__host__ __device__ constexpr CellTab make_cells() {
    CellTab t{};
    t.n = 0;
    for (int K = 0; K <= 8; ++K) {
        int singles[64] = {};
        int ns = 0;
        for (int H = 0; H < 16; ++H) {
            int ls[16] = {};
            int m = 0;
            for (int L = 0; L < 16; ++L) {
                int P = (H << 4) | L;
                if (TBL.present[P] && popc8(P) == K) ls[m++] = L;
            }
            int i = 0;
            while (i < m) {
                int c = (m - i >= 4) ? 4 : (m - i);
                if (c == 1) { singles[ns++] = (H << 4) | ls[i]; i += 1; continue; }
                int id = t.n++;
                t.k[id] = K; t.isL[id] = 0; t.shared[id] = H; t.cnt[id] = c;
                for (int j = 0; j < 4; ++j) {
                    int L = ls[i + (j < c ? j : c - 1)];
                    t.mem[id][j] = L;
                    t.pat[id][j] = (H << 4) | L;
                }
                i += c;
            }
        }
        for (int L = 0; L < 16; ++L) {
            int hs[16] = {};
            int m = 0;
            for (int si = 0; si < ns; ++si)
                if ((singles[si] & 15) == L) hs[m++] = singles[si] >> 4;
            int i = 0;
            while (i < m) {
                int c = (m - i >= 4) ? 4 : (m - i);
                int id = t.n++;
                t.k[id] = K; t.isL[id] = 1; t.shared[id] = L; t.cnt[id] = c;
                for (int j = 0; j < 4; ++j) {
                    int H = hs[i + (j < c ? j : c - 1)];
                    t.mem[id][j] = H;
                    t.pat[id][j] = (H << 4) | L;
                }
                i += c;
            }
        }
    }
    return t;
}

constexpr CellTab CT = make_cells();

// ---------------------------------------------------------------------------
// R11 round-robin emission order (bit-identical permutation).
// ---------------------------------------------------------------------------
struct Order { int idx[224]; };

__host__ __device__ constexpr Order make_order() {
    Order o{};
    int ids[9][64] = {};
    int cg[9] = {};
    for (int i = 0; i < CT.n; ++i) {
        int g = CT.k[i];
        ids[g][cg[g]++] = i;
    }
    int ptr[9] = {};
    int e = 0;
    while (e < CT.n) {
        for (int g = 0; g < 9; ++g) {
            if (ptr[g] < cg[g]) o.idx[e++] = ids[g][ptr[g]++];
        }
    }
    return o;
}

constexpr Order ORD = make_order();

// First emission of this cell's popcount group in ORD order?
__host__ __device__ constexpr bool first_occ(int pos) {
    int g = CT.k[ORD.idx[pos]];
    for (int e = 0; e < pos; ++e)
        if (CT.k[ORD.idx[e]] == g) return false;
    return true;
}

__host__ __device__ constexpr bool group_empty(int K) {
    for (int i = 0; i < CT.n; ++i)
        if (CT.k[i] == K) return false;
    return true;
}

// ---------------------------------------------------------------------------
// Per-thread scan state (compile-time indexed -> registers).
// ---------------------------------------------------------------------------
struct St {
    float ulo[16];
    float th2[16];
    float gmax[9];
    unsigned qid[9];
};

template <int I, bool FIRST>
__device__ __forceinline__ void cstep(St& s) {
    constexpr int K   = CT.k[I];
    constexpr int c   = CT.cnt[I];
    constexpr int IsL = CT.isL[I];
    constexpr int SH  = CT.shared[I];
    constexpr int M0  = CT.mem[I][0];
    constexpr int M1  = CT.mem[I][1];
    constexpr int M2  = CT.mem[I][2];
    constexpr int M3  = CT.mem[I][3];
    constexpr unsigned qid =
        (unsigned)CT.pat[I][0] | ((unsigned)CT.pat[I][1] << 8) |
        ((unsigned)CT.pat[I][2] << 16) | ((unsigned)CT.pat[I][3] << 24);
    float m;
    if constexpr (IsL == 0) {
        m = s.ulo[M0];
        if constexpr (c > 1) m = fmaxf(m, s.ulo[M1]);
        if constexpr (c > 2) m = fmaxf(m, s.ulo[M2]);
        if constexpr (c > 3) m = fmaxf(m, s.ulo[M3]);
        if constexpr (SH != 0) m = m + s.th2[SH];
    } else {
        m = s.th2[M0];
        if constexpr (c > 1) m = fmaxf(m, s.th2[M1]);
        if constexpr (c > 2) m = fmaxf(m, s.th2[M2]);
        if constexpr (c > 3) m = fmaxf(m, s.th2[M3]);
        m = m + s.ulo[SH];
    }
    if constexpr (FIRST) {
        // First cell of its group: direct assignment (identical to the old
        // compare-vs-(-1) init since m >= 0 > -1 always wins).
        s.gmax[K] = m;
        s.qid[K]  = qid;
    } else {
        float old = s.gmax[K];
        s.gmax[K] = fmaxf(old, m);
        s.qid[K] = (m > old) ? qid : s.qid[K];
    }
}

template <int I>
__device__ __forceinline__ void ostep(St& s) {
    if constexpr (I < CT.n) {
        constexpr int J = ORD.idx[I];
        constexpr bool F = first_occ(I);
        cstep<J, F>(s);
    }
}

template <size_t... Is>
__device__ __forceinline__ void run_all(St& s, std::index_sequence<Is...>) {
    (ostep<(int)Is>(s), ...);
}

// Emit -1 init only for groups with no cells (phase-2 then scores them < 0).
template <int K>
__device__ __forceinline__ void init_empty(St& s) {
    if constexpr (K < 9 && group_empty(K)) { s.gmax[K] = -1.f; s.qid[K] = 0u; }
}

// ---------------------------------------------------------------------------
// Main kernel: one thread per 8-element block. 128-thread CTAs; NO
// min-blocks clause (R5 lesson: reg caps cause spills), NO smem (R12).
// ---------------------------------------------------------------------------
__global__ void __launch_bounds__(128)
iq2xs_kernel(const float* __restrict__ w, float* __restrict__ out, int nb) {
    int b = blockIdx.x * 128 + threadIdx.x;
    if (b >= nb) return;

    const float4* w4 = reinterpret_cast<const float4*>(w) + 2 * (size_t)b;
    float4 v0 = w4[0];
    float4 v1 = w4[1];

    // Doubled magnitudes: a2[i] = |w_i| + |w_i| (FADD with abs modifiers).
    float a2[8] = {fabsf(v0.x) + fabsf(v0.x), fabsf(v0.y) + fabsf(v0.y),
                   fabsf(v0.z) + fabsf(v0.z), fabsf(v0.w) + fabsf(v0.w),
                   fabsf(v1.x) + fabsf(v1.x), fabsf(v1.y) + fabsf(v1.y),
                   fabsf(v1.z) + fabsf(v1.z), fabsf(v1.w) + fabsf(v1.w)};

    // Subset-sum DP on doubled magnitudes (exactly 2x the undoubled sums).
    float tlo2[16], thi2[16];
    tlo2[0] = 0.f;
    tlo2[1] = a2[0];
    tlo2[2] = a2[1];
    tlo2[3] = tlo2[1] + a2[1];
    tlo2[4] = a2[2];
    tlo2[5] = tlo2[1] + a2[2];
    tlo2[6] = tlo2[2] + a2[2];
    tlo2[7] = tlo2[3] + a2[2];
#pragma unroll
    for (int m = 0; m < 8; ++m) tlo2[8 + m] = tlo2[m] + a2[3];

    thi2[0] = 0.f;
    thi2[1] = a2[4];
    thi2[2] = a2[5];
    thi2[3] = thi2[1] + a2[5];
    thi2[4] = a2[6];
    thi2[5] = thi2[1] + a2[6];
    thi2[6] = thi2[2] + a2[6];
    thi2[7] = thi2[3] + a2[6];
#pragma unroll
    for (int m = 0; m < 8; ++m) thi2[8 + m] = thi2[m] + a2[7];

    // S = sum of |w| (exact halving of the doubled total)
    float S = 0.5f * (tlo2[15] + thi2[15]);

    St s;
#pragma unroll
    for (int l = 0; l < 16; ++l) s.ulo[l] = S + tlo2[l];   // == fmaf(2,tlo,S)
#pragma unroll
    for (int h = 0; h < 16; ++h) s.th2[h] = thi2[h];       // == 2*thi

    // Init only for empty groups (if any); others direct-assigned in scan.
    init_empty<0>(s); init_empty<1>(s); init_empty<2>(s);
    init_empty<3>(s); init_empty<4>(s); init_empty<5>(s);
    init_empty<6>(s); init_empty<7>(s); init_empty<8>(s);

    // Phase 1: fully unrolled factored-cell scan, round-robin interleaved.
    run_all(s, std::make_index_sequence<224>{});

    // Phase 2 (EXACT R4 form): score = u * |u| * (1/(8+8k)). First group
    // direct-assigned (if empty, sc = -0.125 loses to any real group's
    // sc >= 0 under strict '>').
    float g0 = s.gmax[0];
    float bestSc = g0 * fabsf(g0) * 0.125f;
    unsigned bestQ = s.qid[0];
#pragma unroll
    for (int k = 1; k < 9; ++k) {
        float g = s.gmax[k];
        float sc = g * fabsf(g) * (1.f / (8.f + 8.f * (float)k));
        float oldSc = bestSc;
        bestSc = fmaxf(oldSc, sc);
        bestQ = (sc > oldSc) ? s.qid[k] : bestQ;
    }

    // Reload w (L1 hit) for resolve + epilogue.
    v0 = w4[0];
    v1 = w4[1];
    float wv[8] = {v0.x, v0.y, v0.z, v0.w, v1.x, v1.y, v1.z, v1.w};

    // Phase 3: resolve within the winning cell (branchless, 4 candidates,
    // wv-recompute -- the R11 form). Ascending byte order + strict '>' keeps
    // first-wins; padded duplicates tie and skip.
    int bestP = (int)(bestQ & 255u);
    float bestU;
    {
        float t = 0.f;
#pragma unroll
        for (int i = 0; i < 8; ++i)
            if (bestP & (1 << i)) t += fabsf(wv[i]);
        bestU = fmaf(2.f, t, S);
    }
#pragma unroll
    for (int j = 1; j < 4; ++j) {
        int P = (int)((bestQ >> (8 * j)) & 255u);
        float t = 0.f;
#pragma unroll
        for (int i = 0; i < 8; ++i)
            if (P & (1 << i)) t += fabsf(wv[i]);
        float u = fmaf(2.f, t, S);
        if (u > bestU) { bestU = u; bestP = P; }
    }

    // Least-squares scale; norm recomputed exactly from the winning popcount.
    float norm = (float)(8 * (1 + __popc((unsigned)bestP)));
    float scale = bestU / norm;
    float s3 = 3.f * scale;

    // R15: output deq directly. The reference's STE value w + (deq - w)
    // differs from deq by <= ~ulp(w) per element (output-only rounding,
    // no selection impact); contribution to global rel_err ~1e-7 << 1e-3.
    // sign(+-0)=0 -> deq 0.
    float o[8];
#pragma unroll
    for (int i = 0; i < 8; ++i) {
        float m = ((bestP >> i) & 1) ? s3 : scale;
        o[i] = (wv[i] == 0.f) ? 0.f : copysignf(m, wv[i]);
    }

    float4 r0 = {o[0], o[1], o[2], o[3]};
    float4 r1 = {o[4], o[5], o[6], o[7]};
    float4* out4 = reinterpret_cast<float4*>(out) + 2 * (size_t)b;
    out4[0] = r0;
    out4[1] = r1;
}

extern "C" void kernel_launch(void* const* d_in, const int* in_sizes, int n_in,
                              void* d_out, int out_size) {
    const float* w = (const float*)d_in[0];
    float* out = (float*)d_out;
    int n = in_sizes[0];
    int nb = n / 8;
    int threads = 128;
    int blocks = (nb + threads - 1) / threads;
    iq2xs_kernel<<<blocks, threads>>>(w, out, nb);
}